// round 1
// baseline (speedup 1.0000x reference)
#include <cuda_runtime.h>
#include <cstdint>
#include <cstddef>

// ---------------------------------------------------------------------------
// DeepFM on GB300 — round 1: correct multi-kernel pipeline.
//   out[n] = sum_f e1 + sum_e fm2 + sum_c h3 + bias
// Pipeline:
//   0. detect Xi dtype (int32 vs int64)
//   1. embed: gather W2 rows -> deep (N x 2496), compute e1+fm2 partial out
//   2. GEMM1 (+bias) -> z ; BN stats (fp64 partials) ; finalize ; apply ReLU -> h
//   3. GEMM2 ; BN ; 4. GEMM3 ; BN ; 5. row-sum of h3 added into out
// ---------------------------------------------------------------------------

#define NROWS 16384
#define FDIM  39
#define VDIM  50000
#define EDIM  64
#define KDEEP (FDIM * EDIM)   // 2496
#define C1 1024
#define C2 512
#define C3 256
#define BN_EPS 1e-5f
#define NSLICE 32             // row slices for BN stats

// -------- scratch (device globals: allocation-free rule) --------
__device__ float  g_deep[(size_t)NROWS * KDEEP];   // 163.6 MB
__device__ float  g_z[(size_t)NROWS * C1];         // 67 MB
__device__ float  g_h[(size_t)NROWS * C1];         // 67 MB
__device__ double g_psum[NSLICE * C1];
__device__ double g_psq [NSLICE * C1];
__device__ float  g_scale[C1];
__device__ float  g_shift[C1];
__device__ int    g_idx64;

// -------- 0. dtype detection for Xi --------
__global__ void detect_idx_kernel(const unsigned int* xi_words) {
    // If Xi is int64 (values < 2^31), every odd 32-bit word of the first 32
    // entries is 0. Probability of that for random int32 indices ~ 0.
    unsigned int acc = 0;
    for (int i = 1; i < 64; i += 2) acc |= xi_words[i];
    g_idx64 = (acc == 0) ? 1 : 0;
}

// -------- 1. embedding gather + FM terms --------
// blockDim = (64, 4): 64 e-threads, 4 rows per block. grid = N/4.
__global__ void embed_kernel(const void* __restrict__ Xi_raw,
                             const float* __restrict__ Xv,
                             const float* __restrict__ W1,
                             const float* __restrict__ W2,
                             const float* __restrict__ bias,
                             float* __restrict__ out) {
    const int tx = threadIdx.x;           // 0..63 (embedding dim)
    const int ty = threadIdx.y;           // 0..3  (row within block)
    const int n  = blockIdx.x * 4 + ty;
    const bool is64 = (g_idx64 != 0);
    const long long* Xi64 = (const long long*)Xi_raw;
    const int*       Xi32 = (const int*)Xi_raw;

    float s = 0.f, sq = 0.f;
    #pragma unroll 1
    for (int f = 0; f < FDIM; ++f) {
        int idx = is64 ? (int)Xi64[(size_t)n * FDIM + f] : Xi32[(size_t)n * FDIM + f];
        float xv = Xv[(size_t)n * FDIM + f];
        float w  = W2[((size_t)f * VDIM + idx) * EDIM + tx] * xv;
        g_deep[(size_t)n * KDEEP + f * EDIM + tx] = w;
        s += w; sq += w * w;
    }
    float v = 0.5f * (s * s - sq);        // fm2 contribution for this e
    if (tx < FDIM) {                       // first-order term (feature tx)
        int idx = is64 ? (int)Xi64[(size_t)n * FDIM + tx] : Xi32[(size_t)n * FDIM + tx];
        v += W1[(size_t)tx * VDIM + idx] * Xv[(size_t)n * FDIM + tx];
    }
    // reduce over the 64 threads of this row (2 full warps)
    #pragma unroll
    for (int off = 16; off > 0; off >>= 1) v += __shfl_down_sync(0xffffffffu, v, off);
    __shared__ float red[4][2];
    if ((tx & 31) == 0) red[ty][tx >> 5] = v;
    __syncthreads();
    if (tx == 0) out[n] = red[ty][0] + red[ty][1] + bias[0];
}

// -------- 2. SGEMM with bias: C = A(MxK) @ B(KxNc) + bias --------
// 128x128 tile, BK=8, 256 threads, 8x8 micro-tile per thread.
__global__ void __launch_bounds__(256)
sgemm_bias_kernel(const float* __restrict__ A, const float* __restrict__ B,
                  const float* __restrict__ bias, float* __restrict__ C,
                  int Nc, int K) {
    const int BM = 128, BN = 128, BK = 8;
    __shared__ float As[BK][BM];
    __shared__ float Bs[BK][BN];
    const int tid = threadIdx.x;
    const int m0 = blockIdx.y * BM;
    const int n0 = blockIdx.x * BN;
    const int ty = tid >> 4;          // 0..15
    const int tx = tid & 15;          // 0..15
    const int arow = tid >> 1;        // 0..127
    const int acol = (tid & 1) * 4;   // 0 or 4
    const int brow = tid >> 5;        // 0..7
    const int bcol = (tid & 31) * 4;  // 0..124

    float acc[8][8];
    #pragma unroll
    for (int i = 0; i < 8; ++i)
        #pragma unroll
        for (int j = 0; j < 8; ++j) acc[i][j] = 0.f;

    const float* Aptr = A + (size_t)(m0 + arow) * K + acol;
    const float* Bptr = B + (size_t)brow * Nc + n0 + bcol;

    for (int k0 = 0; k0 < K; k0 += BK) {
        float4 av = *(const float4*)(Aptr + k0);
        As[acol + 0][arow] = av.x;
        As[acol + 1][arow] = av.y;
        As[acol + 2][arow] = av.z;
        As[acol + 3][arow] = av.w;
        float4 bv = *(const float4*)(Bptr + (size_t)k0 * Nc);
        *(float4*)&Bs[brow][bcol] = bv;
        __syncthreads();
        #pragma unroll
        for (int kk = 0; kk < BK; ++kk) {
            float a[8], b[8];
            #pragma unroll
            for (int i = 0; i < 8; ++i) a[i] = As[kk][ty * 8 + i];
            #pragma unroll
            for (int j = 0; j < 8; ++j) b[j] = Bs[kk][tx * 8 + j];
            #pragma unroll
            for (int i = 0; i < 8; ++i)
                #pragma unroll
                for (int j = 0; j < 8; ++j) acc[i][j] += a[i] * b[j];
        }
        __syncthreads();
    }
    #pragma unroll
    for (int i = 0; i < 8; ++i) {
        const int m = m0 + ty * 8 + i;
        #pragma unroll
        for (int j = 0; j < 8; j += 4) {
            const int n = n0 + tx * 8 + j;
            float4 r;
            r.x = acc[i][j + 0] + bias[n + 0];
            r.y = acc[i][j + 1] + bias[n + 1];
            r.z = acc[i][j + 2] + bias[n + 2];
            r.w = acc[i][j + 3] + bias[n + 3];
            *(float4*)&C[(size_t)m * Nc + n] = r;
        }
    }
}

// -------- 3. BN stats: per-column partial sum / sumsq over a 512-row slice --------
// grid (C/128, NSLICE), block 128
__global__ void bn_stats_kernel(const float* __restrict__ z, int C) {
    const int col   = blockIdx.x * 128 + threadIdx.x;
    const int slice = blockIdx.y;
    const int rows  = NROWS / NSLICE;   // 512
    const float* p = z + (size_t)slice * rows * C + col;
    double s = 0.0, ss = 0.0;
    for (int r = 0; r < rows; ++r) {
        float v = p[(size_t)r * C];
        s += v; ss += (double)v * v;
    }
    g_psum[slice * C + col] = s;
    g_psq [slice * C + col] = ss;
}

__global__ void bn_finalize_kernel(const float* __restrict__ g,
                                   const float* __restrict__ b, int C) {
    const int col = blockIdx.x * blockDim.x + threadIdx.x;
    if (col >= C) return;
    double s = 0.0, ss = 0.0;
    for (int i = 0; i < NSLICE; ++i) { s += g_psum[i * C + col]; ss += g_psq[i * C + col]; }
    double mean = s / (double)NROWS;
    double var  = ss / (double)NROWS - mean * mean;
    float sc = g[col] * rsqrtf((float)var + BN_EPS);
    g_scale[col] = sc;
    g_shift[col] = b[col] - (float)mean * sc;
}

// -------- 4. BN + ReLU elementwise (C is a power of two -> mask) --------
__global__ void bn_apply_kernel(const float* __restrict__ z, float* __restrict__ h,
                                size_t total, int cmask) {
    size_t stride = (size_t)gridDim.x * blockDim.x;
    for (size_t i = (size_t)blockIdx.x * blockDim.x + threadIdx.x; i < total; i += stride) {
        int col = (int)(i & (size_t)cmask);
        h[i] = fmaxf(fmaf(z[i], g_scale[col], g_shift[col]), 0.f);
    }
}

// -------- 5. row-sum of h3 (N x 256) added into out --------
__global__ void rowsum_add_kernel(const float* __restrict__ h, float* __restrict__ out) {
    const int gwarp = (blockIdx.x * blockDim.x + threadIdx.x) >> 5;
    const int lane  = threadIdx.x & 31;
    if (gwarp >= NROWS) return;
    const float* p = h + (size_t)gwarp * C3;
    float s = 0.f;
    #pragma unroll
    for (int j = lane; j < C3; j += 32) s += p[j];
    #pragma unroll
    for (int off = 16; off > 0; off >>= 1) s += __shfl_down_sync(0xffffffffu, s, off);
    if (lane == 0) out[gwarp] += s;
}

// ---------------------------------------------------------------------------
extern "C" void kernel_launch(void* const* d_in, const int* in_sizes, int n_in,
                              void* d_out, int out_size) {
    const void*  Xi   = d_in[0];
    const float* Xv   = (const float*)d_in[1];
    const float* W1   = (const float*)d_in[2];
    const float* W2   = (const float*)d_in[3];
    const float* bias = (const float*)d_in[4];
    const float* lw1  = (const float*)d_in[5];
    const float* lb1  = (const float*)d_in[6];
    const float* g1   = (const float*)d_in[7];
    const float* b1   = (const float*)d_in[8];
    const float* lw2  = (const float*)d_in[9];
    const float* lb2  = (const float*)d_in[10];
    const float* g2   = (const float*)d_in[11];
    const float* b2   = (const float*)d_in[12];
    const float* lw3  = (const float*)d_in[13];
    const float* lb3  = (const float*)d_in[14];
    const float* g3   = (const float*)d_in[15];
    const float* b3   = (const float*)d_in[16];
    float* out = (float*)d_out;

    float* deep; cudaGetSymbolAddress((void**)&deep, g_deep);
    float* z;    cudaGetSymbolAddress((void**)&z,    g_z);
    float* h;    cudaGetSymbolAddress((void**)&h,    g_h);

    // 0. dtype detection
    detect_idx_kernel<<<1, 1>>>((const unsigned int*)Xi);

    // 1. embed / FM
    dim3 ebt(64, 4);
    embed_kernel<<<NROWS / 4, ebt>>>(Xi, Xv, W1, W2, bias, out);

    // Layer 1: 2496 -> 1024
    {
        dim3 grid(C1 / 128, NROWS / 128);
        sgemm_bias_kernel<<<grid, 256>>>(deep, lw1, lb1, z, C1, KDEEP);
        dim3 sg(C1 / 128, NSLICE);
        bn_stats_kernel<<<sg, 128>>>(z, C1);
        bn_finalize_kernel<<<(C1 + 255) / 256, 256>>>(g1, b1, C1);
        bn_apply_kernel<<<1024, 256>>>(z, h, (size_t)NROWS * C1, C1 - 1);
    }
    // Layer 2: 1024 -> 512
    {
        dim3 grid(C2 / 128, NROWS / 128);
        sgemm_bias_kernel<<<grid, 256>>>(h, lw2, lb2, z, C2, C1);
        dim3 sg(C2 / 128, NSLICE);
        bn_stats_kernel<<<sg, 128>>>(z, C2);
        bn_finalize_kernel<<<(C2 + 255) / 256, 256>>>(g2, b2, C2);
        bn_apply_kernel<<<1024, 256>>>(z, h, (size_t)NROWS * C2, C2 - 1);
    }
    // Layer 3: 512 -> 256
    {
        dim3 grid(C3 / 128, NROWS / 128);
        sgemm_bias_kernel<<<grid, 256>>>(h, lw3, lb3, z, C3, C2);
        dim3 sg(C3 / 128, NSLICE);
        bn_stats_kernel<<<sg, 128>>>(z, C3);
        bn_finalize_kernel<<<(C3 + 255) / 256, 256>>>(g3, b3, C3);
        bn_apply_kernel<<<1024, 256>>>(z, h, (size_t)NROWS * C3, C3 - 1);
    }
    // 5. final row-sum into out
    rowsum_add_kernel<<<(NROWS * 32 + 255) / 256, 256>>>(h, out);
}

// round 3
// speedup vs baseline: 2.1445x; 2.1445x over previous
#include <cuda_runtime.h>
#include <cuda_bf16.h>
#include <cstdint>
#include <cstddef>

// ---------------------------------------------------------------------------
// DeepFM on GB300 — round 3: mma.sync (HMMA) bf16 hi/lo 3-product GEMMs.
// tcgen05 is unavailable (harness compiles for compute_103, not 103a), so we
// use the compute_80+ tensor path: ldmatrix + mma.sync + cp.async pipeline.
// ---------------------------------------------------------------------------

#define NROWS 16384
#define FDIM  39
#define VDIM  50000
#define EDIM  64
#define KDEEP (FDIM * EDIM)   // 2496
#define C1 1024
#define C2 512
#define C3 256
#define BN_EPS 1e-5f
#define NSLICE 128

// ----------------- scratch (device globals) -----------------
__device__ __align__(1024) __nv_bfloat16 g_deep_hi[(size_t)NROWS * KDEEP];
__device__ __align__(1024) __nv_bfloat16 g_deep_lo[(size_t)NROWS * KDEEP];
__device__ __align__(1024) float         g_z[(size_t)NROWS * C1];
__device__ __align__(1024) __nv_bfloat16 g_h_hi[(size_t)NROWS * C1];
__device__ __align__(1024) __nv_bfloat16 g_h_lo[(size_t)NROWS * C1];
__device__ __align__(1024) __nv_bfloat16 g_bt_hi[(size_t)KDEEP * C1];  // (C x K)
__device__ __align__(1024) __nv_bfloat16 g_bt_lo[(size_t)KDEEP * C1];
__device__ double g_psum[NSLICE * C1];
__device__ double g_psq [NSLICE * C1];
__device__ float  g_scale[C1];
__device__ float  g_shift[C1];
__device__ int    g_idx64;

// ----------------- PTX helpers -----------------
__device__ __forceinline__ uint32_t smem_u32(const void* p) {
    uint32_t a;
    asm("{ .reg .u64 t; cvta.to.shared.u64 t, %1; cvt.u32.u64 %0, t; }" : "=r"(a) : "l"(p));
    return a;
}
#define CP_ASYNC16(dst, src) asm volatile("cp.async.cg.shared.global [%0], [%1], 16;" :: "r"(dst), "l"(src))
#define CP_COMMIT()          asm volatile("cp.async.commit_group;" ::: "memory")
#define CP_WAIT(n)           asm volatile("cp.async.wait_group %0;" :: "n"(n) : "memory")

__device__ __forceinline__ void ldsm_x4(uint32_t* r, uint32_t addr) {
    asm volatile("ldmatrix.sync.aligned.m8n8.x4.shared.b16 {%0,%1,%2,%3}, [%4];"
                 : "=r"(r[0]), "=r"(r[1]), "=r"(r[2]), "=r"(r[3]) : "r"(addr));
}
__device__ __forceinline__ void ldsm_x2(uint32_t* r, uint32_t addr) {
    asm volatile("ldmatrix.sync.aligned.m8n8.x2.shared.b16 {%0,%1}, [%2];"
                 : "=r"(r[0]), "=r"(r[1]) : "r"(addr));
}
__device__ __forceinline__ void mma_bf16(float* c, const uint32_t* a, const uint32_t* b) {
    asm volatile("mma.sync.aligned.m16n8k16.row.col.f32.bf16.bf16.f32 "
                 "{%0,%1,%2,%3}, {%4,%5,%6,%7}, {%8,%9}, {%0,%1,%2,%3};"
                 : "+f"(c[0]), "+f"(c[1]), "+f"(c[2]), "+f"(c[3])
                 : "r"(a[0]), "r"(a[1]), "r"(a[2]), "r"(a[3]), "r"(b[0]), "r"(b[1]));
}

__device__ __forceinline__ void fsplit(float x, __nv_bfloat16& h, __nv_bfloat16& l) {
    h = __float2bfloat16(x);
    l = __float2bfloat16(x - __bfloat162float(h));
}

// ----------------- 0. Xi dtype detection -----------------
__global__ void detect_idx_kernel(const unsigned int* xi_words) {
    unsigned int acc = 0;
    for (int i = 1; i < 64; i += 2) acc |= xi_words[i];
    g_idx64 = (acc == 0) ? 1 : 0;
}

// ----------------- 1. embed + FM -----------------
__global__ void embed_kernel(const void* __restrict__ Xi_raw,
                             const float* __restrict__ Xv,
                             const float* __restrict__ W1,
                             const float* __restrict__ W2,
                             const float* __restrict__ bias,
                             float* __restrict__ out) {
    const int tx = threadIdx.x, ty = threadIdx.y;
    const int n  = blockIdx.x * 4 + ty;
    const bool is64 = (g_idx64 != 0);
    const long long* Xi64 = (const long long*)Xi_raw;
    const int*       Xi32 = (const int*)Xi_raw;

    float s = 0.f, sq = 0.f;
    #pragma unroll 1
    for (int f = 0; f < FDIM; ++f) {
        int idx = is64 ? (int)Xi64[(size_t)n * FDIM + f] : Xi32[(size_t)n * FDIM + f];
        float xv = Xv[(size_t)n * FDIM + f];
        float w  = W2[((size_t)f * VDIM + idx) * EDIM + tx] * xv;
        __nv_bfloat16 h, l; fsplit(w, h, l);
        g_deep_hi[(size_t)n * KDEEP + f * EDIM + tx] = h;
        g_deep_lo[(size_t)n * KDEEP + f * EDIM + tx] = l;
        s += w; sq += w * w;
    }
    float v = 0.5f * (s * s - sq);
    if (tx < FDIM) {
        int idx = is64 ? (int)Xi64[(size_t)n * FDIM + tx] : Xi32[(size_t)n * FDIM + tx];
        v += W1[(size_t)tx * VDIM + idx] * Xv[(size_t)n * FDIM + tx];
    }
    #pragma unroll
    for (int off = 16; off > 0; off >>= 1) v += __shfl_down_sync(0xffffffffu, v, off);
    __shared__ float red[4][2];
    if ((tx & 31) == 0) red[ty][tx >> 5] = v;
    __syncthreads();
    if (tx == 0) out[n] = red[ty][0] + red[ty][1] + bias[0];
}

// ----------------- 2. weight prep: transpose + bf16 split -----------------
__global__ void prep_wt_kernel(const float* __restrict__ W,
                               __nv_bfloat16* __restrict__ Bhi,
                               __nv_bfloat16* __restrict__ Blo, int K, int C) {
    __shared__ float t[32][33];
    const int c0 = blockIdx.x * 32, k0 = blockIdx.y * 32;
    #pragma unroll
    for (int r = threadIdx.y; r < 32; r += 8)
        t[r][threadIdx.x] = W[(size_t)(k0 + r) * C + c0 + threadIdx.x];
    __syncthreads();
    #pragma unroll
    for (int r = threadIdx.y; r < 32; r += 8) {
        float v = t[threadIdx.x][r];
        __nv_bfloat16 h, l; fsplit(v, h, l);
        size_t o = (size_t)(c0 + r) * K + k0 + threadIdx.x;
        Bhi[o] = h; Blo[o] = l;
    }
}

// ----------------- 3. HMMA GEMM: Z = A @ Bt^T + bias -----------------
// A: (M x K) bf16 hi/lo row-major. Bt: (Nc x K) bf16 hi/lo row-major.
// CTA tile 128x128, BK=32, 8 warps (2m x 4n), warp tile 64x32.
#define BM 128
#define BN 128
#define BKC 32
#define SSTRIDE 40                         // bf16 elems per smem row (80 B)
#define TILE_BYTES (128 * SSTRIDE * 2)     // 10240
#define OFF_AHI 0
#define OFF_ALO (TILE_BYTES)
#define OFF_BHI (2 * TILE_BYTES)
#define OFF_BLO (3 * TILE_BYTES)
#define STAGE_BYTES (4 * TILE_BYTES)       // 40960
#define GEMM_SMEM (2 * STAGE_BYTES)        // 81920

__device__ __forceinline__ void issue_stage(uint32_t st, int k0, int K, int tid,
                                            const __nv_bfloat16* A0, const __nv_bfloat16* A1,
                                            const __nv_bfloat16* B0, const __nv_bfloat16* B1) {
    const int row = tid >> 2;            // 0..63
    const int ch  = tid & 3;             // 16B chunk
    const __nv_bfloat16* srcs[4] = { A0, A1, B0, B1 };
    #pragma unroll
    for (int mat = 0; mat < 4; ++mat) {
        #pragma unroll
        for (int h = 0; h < 2; ++h) {
            const int r = row + h * 64;
            CP_ASYNC16(st + mat * TILE_BYTES + (r * SSTRIDE + ch * 8) * 2,
                       srcs[mat] + (size_t)r * K + k0 + ch * 8);
        }
    }
}

__global__ void __launch_bounds__(256, 1)
gemm3_kernel(const __nv_bfloat16* __restrict__ Ahi, const __nv_bfloat16* __restrict__ Alo,
             const __nv_bfloat16* __restrict__ Bhi, const __nv_bfloat16* __restrict__ Blo,
             const float* __restrict__ bias, float* __restrict__ Z, int K, int Nc) {
    extern __shared__ __align__(1024) char smem[];
    const uint32_t sb = smem_u32(smem);
    const int tid = threadIdx.x, wid = tid >> 5, lane = tid & 31;
    const int wm = wid & 1, wn = wid >> 1;           // warp grid 2m x 4n
    const int m0 = blockIdx.y * BM, n0 = blockIdx.x * BN;

    const __nv_bfloat16* A0 = Ahi + (size_t)m0 * K;
    const __nv_bfloat16* A1 = Alo + (size_t)m0 * K;
    const __nv_bfloat16* B0 = Bhi + (size_t)n0 * K;
    const __nv_bfloat16* B1 = Blo + (size_t)n0 * K;

    float acc[4][4][4];
    #pragma unroll
    for (int i = 0; i < 4; ++i)
        #pragma unroll
        for (int j = 0; j < 4; ++j)
            #pragma unroll
            for (int q = 0; q < 4; ++q) acc[i][j][q] = 0.f;

    const int nc = K / BKC;                          // >= 16, even
    issue_stage(sb, 0, K, tid, A0, A1, B0, B1);      CP_COMMIT();
    issue_stage(sb + STAGE_BYTES, BKC, K, tid, A0, A1, B0, B1); CP_COMMIT();

    // per-thread ldmatrix base offsets (elements)
    const uint32_t a_elem = (uint32_t)((wm * 64 + (lane & 15)) * SSTRIDE + (lane >> 4) * 8);
    const uint32_t b_elem = (uint32_t)((wn * 32 + (lane & 7)) * SSTRIDE + ((lane >> 3) & 1) * 8);

    for (int i = 0; i < nc; ++i) {
        CP_WAIT(1);
        __syncthreads();
        const uint32_t st = sb + (uint32_t)(i & 1) * STAGE_BYTES;
        #pragma unroll
        for (int ks = 0; ks < 2; ++ks) {
            uint32_t ahi[4][4], alo[4][4], bhi[4][2], blo[4][2];
            #pragma unroll
            for (int mt = 0; mt < 4; ++mt) {
                const uint32_t ao = st + 2 * (a_elem + mt * 16 * SSTRIDE + ks * 16);
                ldsm_x4(ahi[mt], ao + OFF_AHI);
                ldsm_x4(alo[mt], ao + OFF_ALO);
            }
            #pragma unroll
            for (int nt = 0; nt < 4; ++nt) {
                const uint32_t bo = st + 2 * (b_elem + nt * 8 * SSTRIDE + ks * 16);
                ldsm_x2(bhi[nt], bo + OFF_BHI);
                ldsm_x2(blo[nt], bo + OFF_BLO);
            }
            #pragma unroll
            for (int mt = 0; mt < 4; ++mt)
                #pragma unroll
                for (int nt = 0; nt < 4; ++nt) {
                    mma_bf16(acc[mt][nt], ahi[mt], bhi[nt]);
                    mma_bf16(acc[mt][nt], ahi[mt], blo[nt]);
                    mma_bf16(acc[mt][nt], alo[mt], bhi[nt]);
                }
        }
        __syncthreads();
        if (i + 2 < nc) issue_stage(sb + (uint32_t)(i & 1) * STAGE_BYTES,
                                    (i + 2) * BKC, K, tid, A0, A1, B0, B1);
        CP_COMMIT();
    }

    // epilogue
    #pragma unroll
    for (int nt = 0; nt < 4; ++nt) {
        const int col = n0 + wn * 32 + nt * 8 + (lane & 3) * 2;
        const float b0 = bias[col], b1 = bias[col + 1];
        #pragma unroll
        for (int mt = 0; mt < 4; ++mt) {
            const int row = m0 + wm * 64 + mt * 16 + (lane >> 2);
            float2 v0 = { acc[mt][nt][0] + b0, acc[mt][nt][1] + b1 };
            float2 v1 = { acc[mt][nt][2] + b0, acc[mt][nt][3] + b1 };
            *(float2*)&Z[(size_t)row * Nc + col]       = v0;
            *(float2*)&Z[(size_t)(row + 8) * Nc + col] = v1;
        }
    }
}

// ----------------- 4. BN stats / finalize / apply -----------------
__global__ void bn_stats_kernel(const float* __restrict__ z, int C) {
    const int col   = blockIdx.x * 128 + threadIdx.x;
    const int slice = blockIdx.y;
    const int rows  = NROWS / NSLICE;   // 128
    const float* p = z + (size_t)slice * rows * C + col;
    double s = 0.0, ss = 0.0;
    #pragma unroll 4
    for (int r = 0; r < rows; ++r) {
        float v = p[(size_t)r * C];
        s += v; ss += (double)v * v;
    }
    g_psum[slice * C + col] = s;
    g_psq [slice * C + col] = ss;
}

__global__ void bn_finalize_kernel(const float* __restrict__ g,
                                   const float* __restrict__ b, int C) {
    const int col = blockIdx.x * blockDim.x + threadIdx.x;
    if (col >= C) return;
    double s = 0.0, ss = 0.0;
    for (int i = 0; i < NSLICE; ++i) { s += g_psum[i * C + col]; ss += g_psq[i * C + col]; }
    double mean = s / (double)NROWS;
    double var  = ss / (double)NROWS - mean * mean;
    float sc = g[col] * rsqrtf((float)var + BN_EPS);
    g_scale[col] = sc;
    g_shift[col] = b[col] - (float)mean * sc;
}

__global__ void bn_apply_kernel(const float* __restrict__ z,
                                __nv_bfloat16* __restrict__ hhi,
                                __nv_bfloat16* __restrict__ hlo,
                                size_t total, int cmask) {
    size_t stride = (size_t)gridDim.x * blockDim.x;
    for (size_t i = (size_t)blockIdx.x * blockDim.x + threadIdx.x; i < total; i += stride) {
        int col = (int)(i & (size_t)cmask);
        float v = fmaxf(fmaf(z[i], g_scale[col], g_shift[col]), 0.f);
        __nv_bfloat16 h, l; fsplit(v, h, l);
        hhi[i] = h; hlo[i] = l;
    }
}

// ----------------- 5. fused layer-3 BN + ReLU + row-sum -----------------
__global__ void rowsum_bn_kernel(const float* __restrict__ z, float* __restrict__ out) {
    const int gwarp = (blockIdx.x * blockDim.x + threadIdx.x) >> 5;
    const int lane  = threadIdx.x & 31;
    if (gwarp >= NROWS) return;
    const float* p = z + (size_t)gwarp * C3;
    float s = 0.f;
    #pragma unroll
    for (int j = lane; j < C3; j += 32)
        s += fmaxf(fmaf(p[j], g_scale[j], g_shift[j]), 0.f);
    #pragma unroll
    for (int off = 16; off > 0; off >>= 1) s += __shfl_down_sync(0xffffffffu, s, off);
    if (lane == 0) out[gwarp] += s;
}

// ---------------------------------------------------------------------------
extern "C" void kernel_launch(void* const* d_in, const int* in_sizes, int n_in,
                              void* d_out, int out_size) {
    const void*  Xi   = d_in[0];
    const float* Xv   = (const float*)d_in[1];
    const float* W1   = (const float*)d_in[2];
    const float* W2   = (const float*)d_in[3];
    const float* bias = (const float*)d_in[4];
    const float* lw1  = (const float*)d_in[5];
    const float* lb1  = (const float*)d_in[6];
    const float* g1   = (const float*)d_in[7];
    const float* b1   = (const float*)d_in[8];
    const float* lw2  = (const float*)d_in[9];
    const float* lb2  = (const float*)d_in[10];
    const float* g2   = (const float*)d_in[11];
    const float* b2   = (const float*)d_in[12];
    const float* lw3  = (const float*)d_in[13];
    const float* lb3  = (const float*)d_in[14];
    const float* g3   = (const float*)d_in[15];
    const float* b3   = (const float*)d_in[16];
    float* out = (float*)d_out;

    __nv_bfloat16 *dhi, *dlo, *hhi, *hlo, *bthi, *btlo;
    float *z;
    cudaGetSymbolAddress((void**)&dhi,  g_deep_hi);
    cudaGetSymbolAddress((void**)&dlo,  g_deep_lo);
    cudaGetSymbolAddress((void**)&hhi,  g_h_hi);
    cudaGetSymbolAddress((void**)&hlo,  g_h_lo);
    cudaGetSymbolAddress((void**)&bthi, g_bt_hi);
    cudaGetSymbolAddress((void**)&btlo, g_bt_lo);
    cudaGetSymbolAddress((void**)&z,    g_z);

    cudaFuncSetAttribute(gemm3_kernel, cudaFuncAttributeMaxDynamicSharedMemorySize, GEMM_SMEM);

    detect_idx_kernel<<<1, 1>>>((const unsigned int*)Xi);

    dim3 ebt(64, 4);
    embed_kernel<<<NROWS / 4, ebt>>>(Xi, Xv, W1, W2, bias, out);

    // ---- layer 1: 2496 -> 1024 ----
    {
        prep_wt_kernel<<<dim3(C1 / 32, KDEEP / 32), dim3(32, 8)>>>(lw1, bthi, btlo, KDEEP, C1);
        gemm3_kernel<<<dim3(C1 / BN, NROWS / BM), 256, GEMM_SMEM>>>(dhi, dlo, bthi, btlo, lb1, z, KDEEP, C1);
        bn_stats_kernel<<<dim3(C1 / 128, NSLICE), 128>>>(z, C1);
        bn_finalize_kernel<<<(C1 + 255) / 256, 256>>>(g1, b1, C1);
        bn_apply_kernel<<<2048, 256>>>(z, hhi, hlo, (size_t)NROWS * C1, C1 - 1);
    }
    // ---- layer 2: 1024 -> 512 ----
    {
        prep_wt_kernel<<<dim3(C2 / 32, C1 / 32), dim3(32, 8)>>>(lw2, bthi, btlo, C1, C2);
        gemm3_kernel<<<dim3(C2 / BN, NROWS / BM), 256, GEMM_SMEM>>>(hhi, hlo, bthi, btlo, lb2, z, C1, C2);
        bn_stats_kernel<<<dim3(C2 / 128, NSLICE), 128>>>(z, C2);
        bn_finalize_kernel<<<(C2 + 255) / 256, 256>>>(g2, b2, C2);
        bn_apply_kernel<<<2048, 256>>>(z, hhi, hlo, (size_t)NROWS * C2, C2 - 1);
    }
    // ---- layer 3: 512 -> 256 (BN+ReLU+rowsum fused) ----
    {
        prep_wt_kernel<<<dim3(C3 / 32, C2 / 32), dim3(32, 8)>>>(lw3, bthi, btlo, C2, C3);
        gemm3_kernel<<<dim3(C3 / BN, NROWS / BM), 256, GEMM_SMEM>>>(hhi, hlo, bthi, btlo, lb3, z, C2, C3);
        bn_stats_kernel<<<dim3(C3 / 128, NSLICE), 128>>>(z, C3);
        bn_finalize_kernel<<<(C3 + 255) / 256, 256>>>(g3, b3, C3);
        rowsum_bn_kernel<<<(NROWS * 32 + 255) / 256, 256>>>(z, out);
    }
}

// round 4
// speedup vs baseline: 2.3245x; 1.0839x over previous
#include <cuda_runtime.h>
#include <cuda_bf16.h>
#include <cstdint>
#include <cstddef>

// ---------------------------------------------------------------------------
// DeepFM on GB300 — round 4: HMMA bf16 hi/lo 3-product GEMMs.
//  * 4-stage cp.async pipeline, ONE __syncthreads per k-iter
//  * BN statistics fused into GEMM epilogue (per-rowblock fp32 partials)
//  * 8-wide vectorized BN-apply, x4-paired B ldmatrix
// ---------------------------------------------------------------------------

#define NROWS 16384
#define FDIM  39
#define VDIM  50000
#define EDIM  64
#define KDEEP (FDIM * EDIM)   // 2496
#define C1 1024
#define C2 512
#define C3 256
#define BN_EPS 1e-5f
#define NBLK (NROWS / 128)    // 128 row blocks

// ----------------- scratch (device globals) -----------------
__device__ __align__(1024) __nv_bfloat16 g_deep_hi[(size_t)NROWS * KDEEP];
__device__ __align__(1024) __nv_bfloat16 g_deep_lo[(size_t)NROWS * KDEEP];
__device__ __align__(1024) float         g_z[(size_t)NROWS * C1];
__device__ __align__(1024) __nv_bfloat16 g_h_hi[(size_t)NROWS * C1];
__device__ __align__(1024) __nv_bfloat16 g_h_lo[(size_t)NROWS * C1];
__device__ __align__(1024) __nv_bfloat16 g_bt_hi[(size_t)KDEEP * C1];  // (C x K)
__device__ __align__(1024) __nv_bfloat16 g_bt_lo[(size_t)KDEEP * C1];
__device__ float  g_psumf[NBLK * C1];
__device__ float  g_psqf [NBLK * C1];
__device__ float  g_scale[C1];
__device__ float  g_shift[C1];
__device__ int    g_idx64;

// ----------------- PTX helpers -----------------
__device__ __forceinline__ uint32_t smem_u32(const void* p) {
    uint32_t a;
    asm("{ .reg .u64 t; cvta.to.shared.u64 t, %1; cvt.u32.u64 %0, t; }" : "=r"(a) : "l"(p));
    return a;
}
#define CP_ASYNC16(dst, src) asm volatile("cp.async.cg.shared.global [%0], [%1], 16;" :: "r"(dst), "l"(src))
#define CP_COMMIT()          asm volatile("cp.async.commit_group;" ::: "memory")
#define CP_WAIT(n)           asm volatile("cp.async.wait_group %0;" :: "n"(n) : "memory")

__device__ __forceinline__ void ldsm_x4(uint32_t* r, uint32_t addr) {
    asm volatile("ldmatrix.sync.aligned.m8n8.x4.shared.b16 {%0,%1,%2,%3}, [%4];"
                 : "=r"(r[0]), "=r"(r[1]), "=r"(r[2]), "=r"(r[3]) : "r"(addr));
}
__device__ __forceinline__ void mma_bf16(float* c, const uint32_t* a, const uint32_t* b) {
    asm volatile("mma.sync.aligned.m16n8k16.row.col.f32.bf16.bf16.f32 "
                 "{%0,%1,%2,%3}, {%4,%5,%6,%7}, {%8,%9}, {%0,%1,%2,%3};"
                 : "+f"(c[0]), "+f"(c[1]), "+f"(c[2]), "+f"(c[3])
                 : "r"(a[0]), "r"(a[1]), "r"(a[2]), "r"(a[3]), "r"(b[0]), "r"(b[1]));
}
__device__ __forceinline__ void fsplit(float x, __nv_bfloat16& h, __nv_bfloat16& l) {
    h = __float2bfloat16(x);
    l = __float2bfloat16(x - __bfloat162float(h));
}
__device__ __forceinline__ uint32_t pack2(__nv_bfloat16 a, __nv_bfloat16 b) {
    return (uint32_t)__bfloat16_as_ushort(a) | ((uint32_t)__bfloat16_as_ushort(b) << 16);
}

// ----------------- 0. Xi dtype detection -----------------
__global__ void detect_idx_kernel(const unsigned int* xi_words) {
    unsigned int acc = 0;
    for (int i = 1; i < 64; i += 2) acc |= xi_words[i];
    g_idx64 = (acc == 0) ? 1 : 0;
}

// ----------------- 1. embed + FM -----------------
__global__ void embed_kernel(const void* __restrict__ Xi_raw,
                             const float* __restrict__ Xv,
                             const float* __restrict__ W1,
                             const float* __restrict__ W2,
                             const float* __restrict__ bias,
                             float* __restrict__ out) {
    const int tx = threadIdx.x, ty = threadIdx.y;
    const int n  = blockIdx.x * 4 + ty;
    const bool is64 = (g_idx64 != 0);
    const long long* Xi64 = (const long long*)Xi_raw;
    const int*       Xi32 = (const int*)Xi_raw;

    float s = 0.f, sq = 0.f;
    #pragma unroll 1
    for (int f = 0; f < FDIM; ++f) {
        int idx = is64 ? (int)Xi64[(size_t)n * FDIM + f] : Xi32[(size_t)n * FDIM + f];
        float xv = Xv[(size_t)n * FDIM + f];
        float w  = W2[((size_t)f * VDIM + idx) * EDIM + tx] * xv;
        __nv_bfloat16 h, l; fsplit(w, h, l);
        g_deep_hi[(size_t)n * KDEEP + f * EDIM + tx] = h;
        g_deep_lo[(size_t)n * KDEEP + f * EDIM + tx] = l;
        s += w; sq += w * w;
    }
    float v = 0.5f * (s * s - sq);
    if (tx < FDIM) {
        int idx = is64 ? (int)Xi64[(size_t)n * FDIM + tx] : Xi32[(size_t)n * FDIM + tx];
        v += W1[(size_t)tx * VDIM + idx] * Xv[(size_t)n * FDIM + tx];
    }
    #pragma unroll
    for (int off = 16; off > 0; off >>= 1) v += __shfl_down_sync(0xffffffffu, v, off);
    __shared__ float red[4][2];
    if ((tx & 31) == 0) red[ty][tx >> 5] = v;
    __syncthreads();
    if (tx == 0) out[n] = red[ty][0] + red[ty][1] + bias[0];
}

// ----------------- 2. weight prep: transpose + bf16 split -----------------
__global__ void prep_wt_kernel(const float* __restrict__ W,
                               __nv_bfloat16* __restrict__ Bhi,
                               __nv_bfloat16* __restrict__ Blo, int K, int C) {
    __shared__ float t[32][33];
    const int c0 = blockIdx.x * 32, k0 = blockIdx.y * 32;
    #pragma unroll
    for (int r = threadIdx.y; r < 32; r += 8)
        t[r][threadIdx.x] = W[(size_t)(k0 + r) * C + c0 + threadIdx.x];
    __syncthreads();
    #pragma unroll
    for (int r = threadIdx.y; r < 32; r += 8) {
        float v = t[threadIdx.x][r];
        __nv_bfloat16 h, l; fsplit(v, h, l);
        size_t o = (size_t)(c0 + r) * K + k0 + threadIdx.x;
        Bhi[o] = h; Blo[o] = l;
    }
}

// ----------------- 3. HMMA GEMM + fused BN stats -----------------
// CTA tile 128x128, BK=32, 4-stage cp.async, 8 warps (2m x 4n).
#define BM 128
#define BNT 128
#define BKC 32
#define SSTRIDE 40                         // bf16 elems per smem row (80 B)
#define TILE_BYTES (128 * SSTRIDE * 2)     // 10240
#define OFF_AHI 0
#define OFF_ALO (TILE_BYTES)
#define OFF_BHI (2 * TILE_BYTES)
#define OFF_BLO (3 * TILE_BYTES)
#define STAGE_BYTES (4 * TILE_BYTES)       // 40960
#define NSTAGE 4
#define GEMM_SMEM (NSTAGE * STAGE_BYTES)   // 163840

__device__ __forceinline__ void issue_stage(uint32_t st, int k0, int K, int tid,
                                            const __nv_bfloat16* A0, const __nv_bfloat16* A1,
                                            const __nv_bfloat16* B0, const __nv_bfloat16* B1) {
    const int row = tid >> 2;            // 0..63
    const int ch  = tid & 3;             // 16B chunk
    const __nv_bfloat16* srcs[4] = { A0, A1, B0, B1 };
    #pragma unroll
    for (int mat = 0; mat < 4; ++mat) {
        #pragma unroll
        for (int h = 0; h < 2; ++h) {
            const int r = row + h * 64;
            CP_ASYNC16(st + mat * TILE_BYTES + (r * SSTRIDE + ch * 8) * 2,
                       srcs[mat] + (size_t)r * K + k0 + ch * 8);
        }
    }
}

__global__ void __launch_bounds__(256, 1)
gemm3_kernel(const __nv_bfloat16* __restrict__ Ahi, const __nv_bfloat16* __restrict__ Alo,
             const __nv_bfloat16* __restrict__ Bhi, const __nv_bfloat16* __restrict__ Blo,
             const float* __restrict__ bias, float* __restrict__ Z, int K, int Nc) {
    extern __shared__ __align__(1024) char smem[];
    const uint32_t sb = smem_u32(smem);
    const int tid = threadIdx.x, wid = tid >> 5, lane = tid & 31;
    const int wm = wid & 1, wn = wid >> 1;           // warp grid 2m x 4n
    const int m0 = blockIdx.y * BM, n0 = blockIdx.x * BNT;

    const __nv_bfloat16* A0 = Ahi + (size_t)m0 * K;
    const __nv_bfloat16* A1 = Alo + (size_t)m0 * K;
    const __nv_bfloat16* B0 = Bhi + (size_t)n0 * K;
    const __nv_bfloat16* B1 = Blo + (size_t)n0 * K;

    float acc[4][4][4];
    #pragma unroll
    for (int i = 0; i < 4; ++i)
        #pragma unroll
        for (int j = 0; j < 4; ++j)
            #pragma unroll
            for (int q = 0; q < 4; ++q) acc[i][j][q] = 0.f;

    const int nc = K / BKC;                          // >= 16
    issue_stage(sb + 0 * STAGE_BYTES, 0 * BKC, K, tid, A0, A1, B0, B1); CP_COMMIT();
    issue_stage(sb + 1 * STAGE_BYTES, 1 * BKC, K, tid, A0, A1, B0, B1); CP_COMMIT();
    issue_stage(sb + 2 * STAGE_BYTES, 2 * BKC, K, tid, A0, A1, B0, B1); CP_COMMIT();

    // ldmatrix element offsets
    const uint32_t a_elem = (uint32_t)((wm * 64 + (lane & 15)) * SSTRIDE + (lane >> 4) * 8);
    // B x4: lanes 0-7 -> rows nt (k0), 8-15 -> nt (k8), 16-23 -> nt+1 (k0), 24-31 -> nt+1 (k8)
    const uint32_t b_elem = (uint32_t)((wn * 32 + ((lane >> 4) & 1) * 8 + (lane & 7)) * SSTRIDE
                                       + ((lane >> 3) & 1) * 8);

    for (int i = 0; i < nc; ++i) {
        CP_WAIT(2);
        __syncthreads();
        {
            const int j = i + 3;
            if (j < nc) issue_stage(sb + (uint32_t)(j % NSTAGE) * STAGE_BYTES,
                                    j * BKC, K, tid, A0, A1, B0, B1);
            CP_COMMIT();
        }
        const uint32_t st = sb + (uint32_t)(i % NSTAGE) * STAGE_BYTES;
        #pragma unroll
        for (int ks = 0; ks < 2; ++ks) {
            uint32_t ahi[4][4], alo[4][4], bhi[4][2], blo[4][2];
            #pragma unroll
            for (int mt = 0; mt < 4; ++mt) {
                const uint32_t ao = st + 2 * (a_elem + mt * 16 * SSTRIDE + ks * 16);
                ldsm_x4(ahi[mt], ao + OFF_AHI);
                ldsm_x4(alo[mt], ao + OFF_ALO);
            }
            #pragma unroll
            for (int p = 0; p < 2; ++p) {            // nt pairs (0,1) and (2,3)
                const uint32_t bo = st + 2 * (b_elem + p * 16 * SSTRIDE + ks * 16);
                uint32_t th[4], tl[4];
                ldsm_x4(th, bo + OFF_BHI);
                ldsm_x4(tl, bo + OFF_BLO);
                bhi[2*p][0] = th[0]; bhi[2*p][1] = th[1]; bhi[2*p+1][0] = th[2]; bhi[2*p+1][1] = th[3];
                blo[2*p][0] = tl[0]; blo[2*p][1] = tl[1]; blo[2*p+1][0] = tl[2]; blo[2*p+1][1] = tl[3];
            }
            #pragma unroll
            for (int mt = 0; mt < 4; ++mt)
                #pragma unroll
                for (int nt = 0; nt < 4; ++nt) {
                    mma_bf16(acc[mt][nt], ahi[mt], bhi[nt]);
                    mma_bf16(acc[mt][nt], ahi[mt], blo[nt]);
                    mma_bf16(acc[mt][nt], alo[mt], bhi[nt]);
                }
        }
    }

    // ---------- epilogue: store z + per-CTA BN partial stats ----------
    __syncthreads();
    float* colsum = (float*)smem;          // 128 floats
    float* colsq  = (float*)smem + 128;
    if (tid < 128) { colsum[tid] = 0.f; colsq[tid] = 0.f; }
    __syncthreads();

    #pragma unroll
    for (int nt = 0; nt < 4; ++nt) {
        const int cloc = wn * 32 + nt * 8 + (lane & 3) * 2;
        const int col  = n0 + cloc;
        const float b0 = bias[col], b1 = bias[col + 1];
        float s0 = 0.f, s1 = 0.f, q0 = 0.f, q1 = 0.f;
        #pragma unroll
        for (int mt = 0; mt < 4; ++mt) {
            const int row = m0 + wm * 64 + mt * 16 + (lane >> 2);
            float z00 = acc[mt][nt][0] + b0, z01 = acc[mt][nt][1] + b1;
            float z10 = acc[mt][nt][2] + b0, z11 = acc[mt][nt][3] + b1;
            s0 += z00 + z10;  s1 += z01 + z11;
            q0 += z00 * z00 + z10 * z10;  q1 += z01 * z01 + z11 * z11;
            float2 v0 = { z00, z01 }, v1 = { z10, z11 };
            *(float2*)&Z[(size_t)row * Nc + col]       = v0;
            *(float2*)&Z[(size_t)(row + 8) * Nc + col] = v1;
        }
        #pragma unroll
        for (int off = 16; off >= 4; off >>= 1) {
            s0 += __shfl_down_sync(0xffffffffu, s0, off);
            s1 += __shfl_down_sync(0xffffffffu, s1, off);
            q0 += __shfl_down_sync(0xffffffffu, q0, off);
            q1 += __shfl_down_sync(0xffffffffu, q1, off);
        }
        if ((lane >> 2) == 0) {
            atomicAdd(&colsum[cloc], s0);     atomicAdd(&colsum[cloc + 1], s1);
            atomicAdd(&colsq[cloc],  q0);     atomicAdd(&colsq[cloc + 1],  q1);
        }
    }
    __syncthreads();
    if (tid < 128) {
        g_psumf[(size_t)blockIdx.y * Nc + n0 + tid] = colsum[tid];
        g_psqf [(size_t)blockIdx.y * Nc + n0 + tid] = colsq[tid];
    }
}

// ----------------- 4. BN finalize / apply -----------------
__global__ void bn_finalize_kernel(const float* __restrict__ g,
                                   const float* __restrict__ b, int C) {
    const int col = blockIdx.x * blockDim.x + threadIdx.x;
    if (col >= C) return;
    double s = 0.0, ss = 0.0;
    for (int i = 0; i < NBLK; ++i) { s += g_psumf[i * C + col]; ss += g_psqf[i * C + col]; }
    double mean = s / (double)NROWS;
    double var  = ss / (double)NROWS - mean * mean;
    float sc = g[col] * rsqrtf((float)var + BN_EPS);
    g_scale[col] = sc;
    g_shift[col] = b[col] - (float)mean * sc;
}

// 8 elements per thread iteration
__global__ void bn_apply_kernel(const float* __restrict__ z,
                                uint4* __restrict__ hhi, uint4* __restrict__ hlo,
                                size_t total8, int cmask) {
    const size_t stride = (size_t)gridDim.x * blockDim.x;
    for (size_t t = (size_t)blockIdx.x * blockDim.x + threadIdx.x; t < total8; t += stride) {
        const size_t i = t * 8;
        const int col = (int)(i & (size_t)cmask);
        float4 a = *(const float4*)(z + i);
        float4 c = *(const float4*)(z + i + 4);
        float4 s0 = *(const float4*)(g_scale + col);
        float4 s1 = *(const float4*)(g_scale + col + 4);
        float4 f0 = *(const float4*)(g_shift + col);
        float4 f1 = *(const float4*)(g_shift + col + 4);
        float v[8];
        v[0] = fmaxf(fmaf(a.x, s0.x, f0.x), 0.f);  v[1] = fmaxf(fmaf(a.y, s0.y, f0.y), 0.f);
        v[2] = fmaxf(fmaf(a.z, s0.z, f0.z), 0.f);  v[3] = fmaxf(fmaf(a.w, s0.w, f0.w), 0.f);
        v[4] = fmaxf(fmaf(c.x, s1.x, f1.x), 0.f);  v[5] = fmaxf(fmaf(c.y, s1.y, f1.y), 0.f);
        v[6] = fmaxf(fmaf(c.z, s1.z, f1.z), 0.f);  v[7] = fmaxf(fmaf(c.w, s1.w, f1.w), 0.f);
        uint32_t ph[4], pl[4];
        #pragma unroll
        for (int j = 0; j < 4; ++j) {
            __nv_bfloat16 h0, l0, h1, l1;
            fsplit(v[2 * j], h0, l0); fsplit(v[2 * j + 1], h1, l1);
            ph[j] = pack2(h0, h1); pl[j] = pack2(l0, l1);
        }
        uint4 uh = { ph[0], ph[1], ph[2], ph[3] };
        uint4 ul = { pl[0], pl[1], pl[2], pl[3] };
        hhi[t] = uh; hlo[t] = ul;
    }
}

// ----------------- 5. fused layer-3 BN + ReLU + row-sum -----------------
__global__ void rowsum_bn_kernel(const float* __restrict__ z, float* __restrict__ out) {
    const int gwarp = (blockIdx.x * blockDim.x + threadIdx.x) >> 5;
    const int lane  = threadIdx.x & 31;
    if (gwarp >= NROWS) return;
    const float* p = z + (size_t)gwarp * C3;
    float s = 0.f;
    #pragma unroll
    for (int j = lane; j < C3; j += 32)
        s += fmaxf(fmaf(p[j], g_scale[j], g_shift[j]), 0.f);
    #pragma unroll
    for (int off = 16; off > 0; off >>= 1) s += __shfl_down_sync(0xffffffffu, s, off);
    if (lane == 0) out[gwarp] += s;
}

// ---------------------------------------------------------------------------
extern "C" void kernel_launch(void* const* d_in, const int* in_sizes, int n_in,
                              void* d_out, int out_size) {
    const void*  Xi   = d_in[0];
    const float* Xv   = (const float*)d_in[1];
    const float* W1   = (const float*)d_in[2];
    const float* W2   = (const float*)d_in[3];
    const float* bias = (const float*)d_in[4];
    const float* lw1  = (const float*)d_in[5];
    const float* lb1  = (const float*)d_in[6];
    const float* g1   = (const float*)d_in[7];
    const float* b1   = (const float*)d_in[8];
    const float* lw2  = (const float*)d_in[9];
    const float* lb2  = (const float*)d_in[10];
    const float* g2   = (const float*)d_in[11];
    const float* b2   = (const float*)d_in[12];
    const float* lw3  = (const float*)d_in[13];
    const float* lb3  = (const float*)d_in[14];
    const float* g3   = (const float*)d_in[15];
    const float* b3   = (const float*)d_in[16];
    float* out = (float*)d_out;

    __nv_bfloat16 *dhi, *dlo, *hhi, *hlo, *bthi, *btlo;
    float *z;
    cudaGetSymbolAddress((void**)&dhi,  g_deep_hi);
    cudaGetSymbolAddress((void**)&dlo,  g_deep_lo);
    cudaGetSymbolAddress((void**)&hhi,  g_h_hi);
    cudaGetSymbolAddress((void**)&hlo,  g_h_lo);
    cudaGetSymbolAddress((void**)&bthi, g_bt_hi);
    cudaGetSymbolAddress((void**)&btlo, g_bt_lo);
    cudaGetSymbolAddress((void**)&z,    g_z);

    cudaFuncSetAttribute(gemm3_kernel, cudaFuncAttributeMaxDynamicSharedMemorySize, GEMM_SMEM);

    detect_idx_kernel<<<1, 1>>>((const unsigned int*)Xi);

    dim3 ebt(64, 4);
    embed_kernel<<<NROWS / 4, ebt>>>(Xi, Xv, W1, W2, bias, out);

    // ---- layer 1: 2496 -> 1024 ----
    {
        prep_wt_kernel<<<dim3(C1 / 32, KDEEP / 32), dim3(32, 8)>>>(lw1, bthi, btlo, KDEEP, C1);
        gemm3_kernel<<<dim3(C1 / BNT, NROWS / BM), 256, GEMM_SMEM>>>(dhi, dlo, bthi, btlo, lb1, z, KDEEP, C1);
        bn_finalize_kernel<<<(C1 + 255) / 256, 256>>>(g1, b1, C1);
        bn_apply_kernel<<<1024, 256>>>(z, (uint4*)hhi, (uint4*)hlo, (size_t)NROWS * C1 / 8, C1 - 1);
    }
    // ---- layer 2: 1024 -> 512 ----
    {
        prep_wt_kernel<<<dim3(C2 / 32, C1 / 32), dim3(32, 8)>>>(lw2, bthi, btlo, C1, C2);
        gemm3_kernel<<<dim3(C2 / BNT, NROWS / BM), 256, GEMM_SMEM>>>(hhi, hlo, bthi, btlo, lb2, z, C1, C2);
        bn_finalize_kernel<<<(C2 + 255) / 256, 256>>>(g2, b2, C2);
        bn_apply_kernel<<<1024, 256>>>(z, (uint4*)hhi, (uint4*)hlo, (size_t)NROWS * C2 / 8, C2 - 1);
    }
    // ---- layer 3: 512 -> 256 (BN+ReLU+rowsum fused) ----
    {
        prep_wt_kernel<<<dim3(C3 / 32, C2 / 32), dim3(32, 8)>>>(lw3, bthi, btlo, C2, C3);
        gemm3_kernel<<<dim3(C3 / BNT, NROWS / BM), 256, GEMM_SMEM>>>(hhi, hlo, bthi, btlo, lb3, z, C2, C3);
        bn_finalize_kernel<<<(C3 + 255) / 256, 256>>>(g3, b3, C3);
        rowsum_bn_kernel<<<(NROWS * 32 + 255) / 256, 256>>>(z, out);
    }
}

// round 5
// speedup vs baseline: 4.7608x; 2.0481x over previous
#include <cuda_runtime.h>
#include <cuda_fp16.h>
#include <cstdint>
#include <cstddef>

// ---------------------------------------------------------------------------
// DeepFM on GB300 — round 5: single-product FP16 HMMA GEMMs.
//  * fp16 activations/weights, fp32 accumulate (error ~5e-4/elem << 1e-3 gate)
//  * 2 CTAs/SM (launch_bounds(256,2)), 4-stage cp.async pipeline
//  * BN stats fused into GEMM epilogue
// ---------------------------------------------------------------------------

#define NROWS 16384
#define FDIM  39
#define VDIM  50000
#define EDIM  64
#define KDEEP (FDIM * EDIM)   // 2496
#define C1 1024
#define C2 512
#define C3 256
#define BN_EPS 1e-5f
#define NBLK (NROWS / 128)    // 128 row blocks

// ----------------- scratch (device globals) -----------------
__device__ __align__(1024) __half g_deep[(size_t)NROWS * KDEEP];   // 81.8 MB
__device__ __align__(1024) float  g_z[(size_t)NROWS * C1];         // 67 MB
__device__ __align__(1024) __half g_h[(size_t)NROWS * C1];         // 33.5 MB
__device__ __align__(1024) __half g_bt[(size_t)KDEEP * C1];        // (C x K) 5.1 MB
__device__ float  g_psumf[NBLK * C1];
__device__ float  g_psqf [NBLK * C1];
__device__ float  g_scale[C1];
__device__ float  g_shift[C1];
__device__ int    g_idx64;

// ----------------- PTX helpers -----------------
__device__ __forceinline__ uint32_t smem_u32(const void* p) {
    uint32_t a;
    asm("{ .reg .u64 t; cvta.to.shared.u64 t, %1; cvt.u32.u64 %0, t; }" : "=r"(a) : "l"(p));
    return a;
}
#define CP_ASYNC16(dst, src) asm volatile("cp.async.cg.shared.global [%0], [%1], 16;" :: "r"(dst), "l"(src))
#define CP_COMMIT()          asm volatile("cp.async.commit_group;" ::: "memory")
#define CP_WAIT(n)           asm volatile("cp.async.wait_group %0;" :: "n"(n) : "memory")

__device__ __forceinline__ void ldsm_x4(uint32_t* r, uint32_t addr) {
    asm volatile("ldmatrix.sync.aligned.m8n8.x4.shared.b16 {%0,%1,%2,%3}, [%4];"
                 : "=r"(r[0]), "=r"(r[1]), "=r"(r[2]), "=r"(r[3]) : "r"(addr));
}
__device__ __forceinline__ void mma_f16(float* c, const uint32_t* a, const uint32_t* b) {
    asm volatile("mma.sync.aligned.m16n8k16.row.col.f32.f16.f16.f32 "
                 "{%0,%1,%2,%3}, {%4,%5,%6,%7}, {%8,%9}, {%0,%1,%2,%3};"
                 : "+f"(c[0]), "+f"(c[1]), "+f"(c[2]), "+f"(c[3])
                 : "r"(a[0]), "r"(a[1]), "r"(a[2]), "r"(a[3]), "r"(b[0]), "r"(b[1]));
}
__device__ __forceinline__ uint32_t pack2h(__half a, __half b) {
    return (uint32_t)__half_as_ushort(a) | ((uint32_t)__half_as_ushort(b) << 16);
}

// ----------------- 0. Xi dtype detection -----------------
__global__ void detect_idx_kernel(const unsigned int* xi_words) {
    unsigned int acc = 0;
    for (int i = 1; i < 64; i += 2) acc |= xi_words[i];
    g_idx64 = (acc == 0) ? 1 : 0;
}

// ----------------- 1. embed + FM -----------------
__global__ void embed_kernel(const void* __restrict__ Xi_raw,
                             const float* __restrict__ Xv,
                             const float* __restrict__ W1,
                             const float* __restrict__ W2,
                             const float* __restrict__ bias,
                             float* __restrict__ out) {
    const int tx = threadIdx.x, ty = threadIdx.y;
    const int n  = blockIdx.x * 4 + ty;
    const bool is64 = (g_idx64 != 0);
    const long long* Xi64 = (const long long*)Xi_raw;
    const int*       Xi32 = (const int*)Xi_raw;

    float s = 0.f, sq = 0.f;
    #pragma unroll 1
    for (int f = 0; f < FDIM; ++f) {
        int idx = is64 ? (int)Xi64[(size_t)n * FDIM + f] : Xi32[(size_t)n * FDIM + f];
        float xv = Xv[(size_t)n * FDIM + f];
        float w  = W2[((size_t)f * VDIM + idx) * EDIM + tx] * xv;
        g_deep[(size_t)n * KDEEP + f * EDIM + tx] = __float2half(w);
        s += w; sq += w * w;
    }
    float v = 0.5f * (s * s - sq);
    if (tx < FDIM) {
        int idx = is64 ? (int)Xi64[(size_t)n * FDIM + tx] : Xi32[(size_t)n * FDIM + tx];
        v += W1[(size_t)tx * VDIM + idx] * Xv[(size_t)n * FDIM + tx];
    }
    #pragma unroll
    for (int off = 16; off > 0; off >>= 1) v += __shfl_down_sync(0xffffffffu, v, off);
    __shared__ float red[4][2];
    if ((tx & 31) == 0) red[ty][tx >> 5] = v;
    __syncthreads();
    if (tx == 0) out[n] = red[ty][0] + red[ty][1] + bias[0];
}

// ----------------- 2. weight prep: transpose to fp16 (C x K) -----------------
__global__ void prep_wt_kernel(const float* __restrict__ W,
                               __half* __restrict__ Bt, int K, int C) {
    __shared__ float t[32][33];
    const int c0 = blockIdx.x * 32, k0 = blockIdx.y * 32;
    #pragma unroll
    for (int r = threadIdx.y; r < 32; r += 8)
        t[r][threadIdx.x] = W[(size_t)(k0 + r) * C + c0 + threadIdx.x];
    __syncthreads();
    #pragma unroll
    for (int r = threadIdx.y; r < 32; r += 8)
        Bt[(size_t)(c0 + r) * K + k0 + threadIdx.x] = __float2half(t[threadIdx.x][r]);
}

// ----------------- 3. FP16 HMMA GEMM + fused BN stats -----------------
// CTA tile 128x128, BK=32, 4-stage cp.async, 8 warps (2m x 4n), 2 CTAs/SM.
#define BM 128
#define BNT 128
#define BKC 32
#define SSTRIDE 40                         // fp16 elems per smem row (80 B)
#define TILE_BYTES (128 * SSTRIDE * 2)     // 10240
#define OFF_A 0
#define OFF_B (TILE_BYTES)
#define STAGE_BYTES (2 * TILE_BYTES)       // 20480
#define NSTAGE 4
#define GEMM_SMEM (NSTAGE * STAGE_BYTES)   // 81920

__device__ __forceinline__ void issue_stage(uint32_t st, int k0, int K, int tid,
                                            const __half* A, const __half* B) {
    const int row = tid >> 2;            // 0..63
    const int ch  = tid & 3;             // 16B chunk
    const __half* srcs[2] = { A, B };
    #pragma unroll
    for (int mat = 0; mat < 2; ++mat) {
        #pragma unroll
        for (int h = 0; h < 2; ++h) {
            const int r = row + h * 64;
            CP_ASYNC16(st + mat * TILE_BYTES + (r * SSTRIDE + ch * 8) * 2,
                       srcs[mat] + (size_t)r * K + k0 + ch * 8);
        }
    }
}

__global__ void __launch_bounds__(256, 2)
gemmh_kernel(const __half* __restrict__ Ag, const __half* __restrict__ Bg,
             const float* __restrict__ bias, float* __restrict__ Z, int K, int Nc) {
    extern __shared__ __align__(1024) char smem[];
    const uint32_t sb = smem_u32(smem);
    const int tid = threadIdx.x, wid = tid >> 5, lane = tid & 31;
    const int wm = wid & 1, wn = wid >> 1;           // warp grid 2m x 4n
    const int m0 = blockIdx.y * BM, n0 = blockIdx.x * BNT;

    const __half* A = Ag + (size_t)m0 * K;
    const __half* B = Bg + (size_t)n0 * K;

    float acc[4][4][4];
    #pragma unroll
    for (int i = 0; i < 4; ++i)
        #pragma unroll
        for (int j = 0; j < 4; ++j)
            #pragma unroll
            for (int q = 0; q < 4; ++q) acc[i][j][q] = 0.f;

    const int nc = K / BKC;
    issue_stage(sb + 0 * STAGE_BYTES, 0 * BKC, K, tid, A, B); CP_COMMIT();
    issue_stage(sb + 1 * STAGE_BYTES, 1 * BKC, K, tid, A, B); CP_COMMIT();
    issue_stage(sb + 2 * STAGE_BYTES, 2 * BKC, K, tid, A, B); CP_COMMIT();

    const uint32_t a_elem = (uint32_t)((wm * 64 + (lane & 15)) * SSTRIDE + (lane >> 4) * 8);
    const uint32_t b_elem = (uint32_t)((wn * 32 + ((lane >> 4) & 1) * 8 + (lane & 7)) * SSTRIDE
                                       + ((lane >> 3) & 1) * 8);

    for (int i = 0; i < nc; ++i) {
        CP_WAIT(2);
        __syncthreads();
        {
            const int j = i + 3;
            if (j < nc) issue_stage(sb + (uint32_t)(j % NSTAGE) * STAGE_BYTES,
                                    j * BKC, K, tid, A, B);
            CP_COMMIT();
        }
        const uint32_t st = sb + (uint32_t)(i % NSTAGE) * STAGE_BYTES;
        #pragma unroll
        for (int ks = 0; ks < 2; ++ks) {
            uint32_t a[4][4], b[4][2];
            #pragma unroll
            for (int mt = 0; mt < 4; ++mt)
                ldsm_x4(a[mt], st + OFF_A + 2 * (a_elem + mt * 16 * SSTRIDE + ks * 16));
            #pragma unroll
            for (int p = 0; p < 2; ++p) {
                uint32_t t[4];
                ldsm_x4(t, st + OFF_B + 2 * (b_elem + p * 16 * SSTRIDE + ks * 16));
                b[2*p][0] = t[0]; b[2*p][1] = t[1]; b[2*p+1][0] = t[2]; b[2*p+1][1] = t[3];
            }
            #pragma unroll
            for (int mt = 0; mt < 4; ++mt)
                #pragma unroll
                for (int nt = 0; nt < 4; ++nt)
                    mma_f16(acc[mt][nt], a[mt], b[nt]);
        }
    }

    // ---------- epilogue: store z + per-CTA BN partial stats ----------
    __syncthreads();
    float* colsum = (float*)smem;
    float* colsq  = (float*)smem + 128;
    if (tid < 128) { colsum[tid] = 0.f; colsq[tid] = 0.f; }
    __syncthreads();

    #pragma unroll
    for (int nt = 0; nt < 4; ++nt) {
        const int cloc = wn * 32 + nt * 8 + (lane & 3) * 2;
        const int col  = n0 + cloc;
        const float b0 = bias[col], b1 = bias[col + 1];
        float s0 = 0.f, s1 = 0.f, q0 = 0.f, q1 = 0.f;
        #pragma unroll
        for (int mt = 0; mt < 4; ++mt) {
            const int row = m0 + wm * 64 + mt * 16 + (lane >> 2);
            float z00 = acc[mt][nt][0] + b0, z01 = acc[mt][nt][1] + b1;
            float z10 = acc[mt][nt][2] + b0, z11 = acc[mt][nt][3] + b1;
            s0 += z00 + z10;  s1 += z01 + z11;
            q0 += z00 * z00 + z10 * z10;  q1 += z01 * z01 + z11 * z11;
            float2 v0 = { z00, z01 }, v1 = { z10, z11 };
            *(float2*)&Z[(size_t)row * Nc + col]       = v0;
            *(float2*)&Z[(size_t)(row + 8) * Nc + col] = v1;
        }
        #pragma unroll
        for (int off = 16; off >= 4; off >>= 1) {
            s0 += __shfl_down_sync(0xffffffffu, s0, off);
            s1 += __shfl_down_sync(0xffffffffu, s1, off);
            q0 += __shfl_down_sync(0xffffffffu, q0, off);
            q1 += __shfl_down_sync(0xffffffffu, q1, off);
        }
        if ((lane >> 2) == 0) {
            atomicAdd(&colsum[cloc], s0);     atomicAdd(&colsum[cloc + 1], s1);
            atomicAdd(&colsq[cloc],  q0);     atomicAdd(&colsq[cloc + 1],  q1);
        }
    }
    __syncthreads();
    if (tid < 128) {
        g_psumf[(size_t)blockIdx.y * Nc + n0 + tid] = colsum[tid];
        g_psqf [(size_t)blockIdx.y * Nc + n0 + tid] = colsq[tid];
    }
}

// ----------------- 4. BN finalize / apply -----------------
__global__ void bn_finalize_kernel(const float* __restrict__ g,
                                   const float* __restrict__ b, int C) {
    const int col = blockIdx.x * blockDim.x + threadIdx.x;
    if (col >= C) return;
    double s = 0.0, ss = 0.0;
    for (int i = 0; i < NBLK; ++i) { s += g_psumf[i * C + col]; ss += g_psqf[i * C + col]; }
    double mean = s / (double)NROWS;
    double var  = ss / (double)NROWS - mean * mean;
    float sc = g[col] * rsqrtf((float)var + BN_EPS);
    g_scale[col] = sc;
    g_shift[col] = b[col] - (float)mean * sc;
}

// 8 elements per thread iteration; writes fp16
__global__ void bn_apply_kernel(const float* __restrict__ z,
                                uint4* __restrict__ h,
                                size_t total8, int cmask) {
    const size_t stride = (size_t)gridDim.x * blockDim.x;
    for (size_t t = (size_t)blockIdx.x * blockDim.x + threadIdx.x; t < total8; t += stride) {
        const size_t i = t * 8;
        const int col = (int)(i & (size_t)cmask);
        float4 a = *(const float4*)(z + i);
        float4 c = *(const float4*)(z + i + 4);
        float4 s0 = *(const float4*)(g_scale + col);
        float4 s1 = *(const float4*)(g_scale + col + 4);
        float4 f0 = *(const float4*)(g_shift + col);
        float4 f1 = *(const float4*)(g_shift + col + 4);
        float v[8];
        v[0] = fmaxf(fmaf(a.x, s0.x, f0.x), 0.f);  v[1] = fmaxf(fmaf(a.y, s0.y, f0.y), 0.f);
        v[2] = fmaxf(fmaf(a.z, s0.z, f0.z), 0.f);  v[3] = fmaxf(fmaf(a.w, s0.w, f0.w), 0.f);
        v[4] = fmaxf(fmaf(c.x, s1.x, f1.x), 0.f);  v[5] = fmaxf(fmaf(c.y, s1.y, f1.y), 0.f);
        v[6] = fmaxf(fmaf(c.z, s1.z, f1.z), 0.f);  v[7] = fmaxf(fmaf(c.w, s1.w, f1.w), 0.f);
        uint4 u;
        u.x = pack2h(__float2half(v[0]), __float2half(v[1]));
        u.y = pack2h(__float2half(v[2]), __float2half(v[3]));
        u.z = pack2h(__float2half(v[4]), __float2half(v[5]));
        u.w = pack2h(__float2half(v[6]), __float2half(v[7]));
        h[t] = u;
    }
}

// ----------------- 5. fused layer-3 BN + ReLU + row-sum -----------------
__global__ void rowsum_bn_kernel(const float* __restrict__ z, float* __restrict__ out) {
    const int gwarp = (blockIdx.x * blockDim.x + threadIdx.x) >> 5;
    const int lane  = threadIdx.x & 31;
    if (gwarp >= NROWS) return;
    const float* p = z + (size_t)gwarp * C3;
    float s = 0.f;
    #pragma unroll
    for (int j = lane; j < C3; j += 32)
        s += fmaxf(fmaf(p[j], g_scale[j], g_shift[j]), 0.f);
    #pragma unroll
    for (int off = 16; off > 0; off >>= 1) s += __shfl_down_sync(0xffffffffu, s, off);
    if (lane == 0) out[gwarp] += s;
}

// ---------------------------------------------------------------------------
extern "C" void kernel_launch(void* const* d_in, const int* in_sizes, int n_in,
                              void* d_out, int out_size) {
    const void*  Xi   = d_in[0];
    const float* Xv   = (const float*)d_in[1];
    const float* W1   = (const float*)d_in[2];
    const float* W2   = (const float*)d_in[3];
    const float* bias = (const float*)d_in[4];
    const float* lw1  = (const float*)d_in[5];
    const float* lb1  = (const float*)d_in[6];
    const float* g1   = (const float*)d_in[7];
    const float* b1   = (const float*)d_in[8];
    const float* lw2  = (const float*)d_in[9];
    const float* lb2  = (const float*)d_in[10];
    const float* g2   = (const float*)d_in[11];
    const float* b2   = (const float*)d_in[12];
    const float* lw3  = (const float*)d_in[13];
    const float* lb3  = (const float*)d_in[14];
    const float* g3   = (const float*)d_in[15];
    const float* b3   = (const float*)d_in[16];
    float* out = (float*)d_out;

    __half *deep, *h, *bt;
    float *z;
    cudaGetSymbolAddress((void**)&deep, g_deep);
    cudaGetSymbolAddress((void**)&h,    g_h);
    cudaGetSymbolAddress((void**)&bt,   g_bt);
    cudaGetSymbolAddress((void**)&z,    g_z);

    cudaFuncSetAttribute(gemmh_kernel, cudaFuncAttributeMaxDynamicSharedMemorySize, GEMM_SMEM);

    detect_idx_kernel<<<1, 1>>>((const unsigned int*)Xi);

    dim3 ebt(64, 4);
    embed_kernel<<<NROWS / 4, ebt>>>(Xi, Xv, W1, W2, bias, out);

    // ---- layer 1: 2496 -> 1024 ----
    {
        prep_wt_kernel<<<dim3(C1 / 32, KDEEP / 32), dim3(32, 8)>>>(lw1, bt, KDEEP, C1);
        gemmh_kernel<<<dim3(C1 / BNT, NROWS / BM), 256, GEMM_SMEM>>>(deep, bt, lb1, z, KDEEP, C1);
        bn_finalize_kernel<<<(C1 + 255) / 256, 256>>>(g1, b1, C1);
        bn_apply_kernel<<<1024, 256>>>(z, (uint4*)h, (size_t)NROWS * C1 / 8, C1 - 1);
    }
    // ---- layer 2: 1024 -> 512 ----
    {
        prep_wt_kernel<<<dim3(C2 / 32, C1 / 32), dim3(32, 8)>>>(lw2, bt, C1, C2);
        gemmh_kernel<<<dim3(C2 / BNT, NROWS / BM), 256, GEMM_SMEM>>>(h, bt, lb2, z, C1, C2);
        bn_finalize_kernel<<<(C2 + 255) / 256, 256>>>(g2, b2, C2);
        bn_apply_kernel<<<1024, 256>>>(z, (uint4*)h, (size_t)NROWS * C2 / 8, C2 - 1);
    }
    // ---- layer 3: 512 -> 256 (BN+ReLU+rowsum fused) ----
    {
        prep_wt_kernel<<<dim3(C3 / 32, C2 / 32), dim3(32, 8)>>>(lw3, bt, C2, C3);
        gemmh_kernel<<<dim3(C3 / BNT, NROWS / BM), 256, GEMM_SMEM>>>(h, bt, lb3, z, C2, C3);
        bn_finalize_kernel<<<(C3 + 255) / 256, 256>>>(g3, b3, C3);
        rowsum_bn_kernel<<<(NROWS * 32 + 255) / 256, 256>>>(z, out);
    }
}